// round 8
// baseline (speedup 1.0000x reference)
#include <cuda_runtime.h>
#include <cuda_bf16.h>

#define N_NODES 50000
#define N_EDGES 800000
#define NUM_GRAPHS 256
#define D 64
#define EPS 1e-5f

#define SCHUNK 196
#define SBLOCKS 256   // 256*196 = 50176 >= 50000

// ---------------- scratch (device globals; no allocation) ----------------
__device__ float g_xw[N_NODES * D];      // A@W (layer0: raw; layer1: dinv-folded)
__device__ float g_agg[N_NODES * D];     // layer output
__device__ float g_deg[N_NODES];         // 1 + in-degree (float)
__device__ float g_dinv[N_NODES];
__device__ int   g_esrc[N_EDGES];        // source ids, grouped by target (CSR)
__device__ int   g_startv[N_NODES];      // CSR row start
__device__ int   g_pos[N_NODES];         // placement cursor -> row end
__device__ int   g_part[SBLOCKS];
__device__ float g_pooled[NUM_GRAPHS * D];
__device__ float g_cnt[NUM_GRAPHS];

// ---------------- init: deg=1 (self-loop) + zero pool ----------------
__global__ void k_init() {
    int i = blockIdx.x * blockDim.x + threadIdx.x;
    if (i < N_NODES) g_deg[i] = 1.0f;
    if (i < NUM_GRAPHS * D) g_pooled[i] = 0.0f;
    if (i < NUM_GRAPHS) g_cnt[i] = 0.0f;
}

__global__ void k_deg_count(const int* __restrict__ col) {
    int e = blockIdx.x * blockDim.x + threadIdx.x;
    if (e < N_EDGES) atomicAdd(&g_deg[col[e]], 1.0f);
}

// ---------------- scan phase 1: per-chunk totals (+ dinv fused) ----------------
__global__ void k_scan_partial() {
    __shared__ int sh[256];
    int b = blockIdx.x, t = threadIdx.x;
    int n = b * SCHUNK + t;
    int v = 0;
    if (t < SCHUNK && n < N_NODES) {
        float d = g_deg[n];
        g_dinv[n] = rsqrtf(d);
        v = (int)d - 1;
    }
    sh[t] = v;
    __syncthreads();
    for (int off = 128; off > 0; off >>= 1) {
        if (t < off) sh[t] += sh[t + off];
        __syncthreads();
    }
    if (t == 0) g_part[b] = sh[0];
}

// ---------------- scan phase 2: chunk scan with inline base reduction ----------------
__global__ void k_scan_chunk() {
    __shared__ int sh[256];
    __shared__ int bs[256];
    int b = blockIdx.x, t = threadIdx.x;
    bs[t] = (t < b) ? g_part[t] : 0;
    int n = b * SCHUNK + t;
    int v = 0;
    if (t < SCHUNK && n < N_NODES) v = (int)g_deg[n] - 1;
    sh[t] = v;
    __syncthreads();
    for (int off = 128; off > 0; off >>= 1) {
        if (t < off) bs[t] += bs[t + off];
        __syncthreads();
    }
    for (int off = 1; off < 256; off <<= 1) {
        int add = (t >= off) ? sh[t - off] : 0;
        __syncthreads();
        sh[t] += add;
        __syncthreads();
    }
    if (t < SCHUNK && n < N_NODES) {
        int start = bs[0] + sh[t] - v;
        g_startv[n] = start;
        g_pos[n] = start;
    }
}

__global__ void k_place(const int* __restrict__ row, const int* __restrict__ col) {
    int e = blockIdx.x * blockDim.x + threadIdx.x;
    if (e >= N_EDGES) return;
    int c = col[e];
    int slot = atomicAdd(&g_pos[c], 1);
    g_esrc[slot] = row[e];
}

// ---------------- GEMM: C[n,:] = (A[n,:] @ W) * (use_dinv ? dinv[n] : 1) ----------------
__global__ void k_gemm64(const float* __restrict__ A,
                         const float* __restrict__ W,
                         float* __restrict__ C,
                         int use_dinv) {
    __shared__ float  As[64][65];
    __shared__ float4 Ws4[64][16];
    int tid = threadIdx.x;
    int row0 = blockIdx.x * 64;

    #pragma unroll
    for (int i = tid; i < 1024; i += 256)
        Ws4[i >> 4][i & 15] = ((const float4*)W)[i];
    #pragma unroll
    for (int i = tid; i < 4096; i += 256) {
        int r = i >> 6, c = i & 63;
        As[r][c] = (row0 + r < N_NODES) ? A[(row0 + r) * D + c] : 0.0f;
    }
    __syncthreads();

    int tx = tid & 15;
    int ty = tid >> 4;

    float4 acc0 = {0,0,0,0}, acc1 = {0,0,0,0}, acc2 = {0,0,0,0}, acc3 = {0,0,0,0};

    #pragma unroll
    for (int k = 0; k < 64; k++) {
        float4 w = Ws4[k][tx];
        float a0 = As[ty * 4 + 0][k];
        float a1 = As[ty * 4 + 1][k];
        float a2 = As[ty * 4 + 2][k];
        float a3 = As[ty * 4 + 3][k];
        acc0.x = fmaf(a0, w.x, acc0.x); acc0.y = fmaf(a0, w.y, acc0.y);
        acc0.z = fmaf(a0, w.z, acc0.z); acc0.w = fmaf(a0, w.w, acc0.w);
        acc1.x = fmaf(a1, w.x, acc1.x); acc1.y = fmaf(a1, w.y, acc1.y);
        acc1.z = fmaf(a1, w.z, acc1.z); acc1.w = fmaf(a1, w.w, acc1.w);
        acc2.x = fmaf(a2, w.x, acc2.x); acc2.y = fmaf(a2, w.y, acc2.y);
        acc2.z = fmaf(a2, w.z, acc2.z); acc2.w = fmaf(a2, w.w, acc2.w);
        acc3.x = fmaf(a3, w.x, acc3.x); acc3.y = fmaf(a3, w.y, acc3.y);
        acc3.z = fmaf(a3, w.z, acc3.z); acc3.w = fmaf(a3, w.w, acc3.w);
    }

    #pragma unroll
    for (int i = 0; i < 4; i++) {
        int r = row0 + ty * 4 + i;
        if (r < N_NODES) {
            float d = use_dinv ? g_dinv[r] : 1.0f;
            float4 v = (i == 0) ? acc0 : (i == 1) ? acc1 : (i == 2) ? acc2 : acc3;
            v.x *= d; v.y *= d; v.z *= d; v.w *= d;
            *((float4*)(C + r * D) + tx) = v;
        }
    }
}

// ---------------- gather-aggregate + self-loop + bias + BN + ReLU ----------------
// per_edge_dinv=1: g_xw is raw A@W; apply dinv[r] per message, dinv[w]^2 on self.
// per_edge_dinv=0: g_xw already has dinv folded per row.
__global__ void k_agg(const float* __restrict__ b,
                      const float* __restrict__ bg,
                      const float* __restrict__ bb,
                      const float* __restrict__ bm,
                      const float* __restrict__ bv,
                      int per_edge_dinv) {
    int w = (blockIdx.x * blockDim.x + threadIdx.x) >> 5;
    int lane = threadIdx.x & 31;
    if (w >= N_NODES) return;
    int s0 = g_startv[w];
    int s1 = g_pos[w];
    int cb = 2 * lane;
    float dc = g_dinv[w];

    float2 self = *(const float2*)(g_xw + w * D + cb);
    float2 acc;
    if (per_edge_dinv) {
        acc.x = dc * self.x;
        acc.y = dc * self.y;
        for (int j = s0; j < s1; j++) {
            int r = __ldg(&g_esrc[j]);
            float dr = __ldg(&g_dinv[r]);
            float2 v = *(const float2*)(g_xw + r * D + cb);
            acc.x = fmaf(dr, v.x, acc.x);
            acc.y = fmaf(dr, v.y, acc.y);
        }
    } else {
        acc = self;
        for (int j = s0; j < s1; j++) {
            int r = __ldg(&g_esrc[j]);
            float2 v = *(const float2*)(g_xw + r * D + cb);
            acc.x += v.x;
            acc.y += v.y;
        }
    }
    float2 bj  = *(const float2*)(b  + cb);
    float2 mj  = *(const float2*)(bm + cb);
    float2 vj  = *(const float2*)(bv + cb);
    float2 gj  = *(const float2*)(bg + cb);
    float2 bbj = *(const float2*)(bb + cb);
    float2 o;
    o.x = fmaxf((dc * acc.x + bj.x - mj.x) * rsqrtf(vj.x + EPS) * gj.x + bbj.x, 0.f);
    o.y = fmaxf((dc * acc.y + bj.y - mj.y) * rsqrtf(vj.y + EPS) * gj.y + bbj.y, 0.f);
    *(float2*)(g_agg + w * D + cb) = o;
}

// ---------------- global mean pool: run-length segment reduce ----------------
#define POOL_NODES 200
__global__ void k_pool(const int* __restrict__ batch) {
    int c = threadIdx.x;
    int n0 = blockIdx.x * POOL_NODES;
    int n1 = n0 + POOL_NODES; if (n1 > N_NODES) n1 = N_NODES;
    if (n0 >= N_NODES) return;
    int cur = __ldg(&batch[n0]);
    float acc = 0.f, cnt = 0.f;
    for (int n = n0; n < n1; n++) {
        int bkt = __ldg(&batch[n]);
        if (bkt != cur) {
            atomicAdd(&g_pooled[cur * D + c], acc);
            if (c == 0) atomicAdd(&g_cnt[cur], cnt);
            cur = bkt; acc = 0.f; cnt = 0.f;
        }
        acc += g_agg[n * D + c];
        cnt += 1.f;
    }
    atomicAdd(&g_pooled[cur * D + c], acc);
    if (c == 0) atomicAdd(&g_cnt[cur], cnt);
}

// ---------------- MLP head ----------------
__global__ void k_mlp(const float* __restrict__ hW1, const float* __restrict__ hb1,
                      const float* __restrict__ hg1, const float* __restrict__ hbb1,
                      const float* __restrict__ hm1, const float* __restrict__ hv1,
                      const float* __restrict__ hW2, const float* __restrict__ hb2,
                      const float* __restrict__ hg2, const float* __restrict__ hbb2,
                      const float* __restrict__ hm2, const float* __restrict__ hv2,
                      const float* __restrict__ hW3, const float* __restrict__ hb3,
                      const float* __restrict__ hW4, const float* __restrict__ hb4,
                      float* __restrict__ out) {
    __shared__ float p[64];
    __shared__ float z1[256];
    __shared__ float z2[128];
    __shared__ float z3[64];
    int g = blockIdx.x;
    int tid = threadIdx.x;
    if (tid < 64) {
        float c = fmaxf(g_cnt[g], 1.0f);
        p[tid] = g_pooled[g * D + tid] / c;
    }
    __syncthreads();
    {
        float acc = hb1[tid];
        #pragma unroll
        for (int k = 0; k < 64; k++) acc = fmaf(p[k], hW1[k * 256 + tid], acc);
        acc = (acc - hm1[tid]) * rsqrtf(hv1[tid] + EPS) * hg1[tid] + hbb1[tid];
        z1[tid] = fmaxf(acc, 0.0f);
    }
    __syncthreads();
    if (tid < 128) {
        float acc = hb2[tid];
        #pragma unroll 8
        for (int k = 0; k < 256; k++) acc = fmaf(z1[k], hW2[k * 128 + tid], acc);
        acc = (acc - hm2[tid]) * rsqrtf(hv2[tid] + EPS) * hg2[tid] + hbb2[tid];
        z2[tid] = fmaxf(acc, 0.0f);
    }
    __syncthreads();
    if (tid < 64) {
        float acc = hb3[tid];
        #pragma unroll 8
        for (int k = 0; k < 128; k++) acc = fmaf(z2[k], hW3[k * 64 + tid], acc);
        z3[tid] = fmaxf(acc, 0.0f);
    }
    __syncthreads();
    if (tid == 0) {
        float acc = hb4[0];
        #pragma unroll
        for (int k = 0; k < 64; k++) acc = fmaf(z3[k], hW4[k], acc);
        out[g] = acc;
    }
}

// ---------------- launch ----------------
extern "C" void kernel_launch(void* const* d_in, const int* in_sizes, int n_in,
                              void* d_out, int out_size) {
    const float* x      = (const float*)d_in[0];
    const int*   ei     = (const int*)d_in[1];
    const int*   batch  = (const int*)d_in[2];
    const float* gcn_W0 = (const float*)d_in[3];
    const float* gcn_b0 = (const float*)d_in[4];
    const float* bn_g0  = (const float*)d_in[5];
    const float* bn_b0  = (const float*)d_in[6];
    const float* bn_m0  = (const float*)d_in[7];
    const float* bn_v0  = (const float*)d_in[8];
    const float* gcn_W1 = (const float*)d_in[9];
    const float* gcn_b1 = (const float*)d_in[10];
    const float* bn_g1  = (const float*)d_in[11];
    const float* bn_b1  = (const float*)d_in[12];
    const float* bn_m1  = (const float*)d_in[13];
    const float* bn_v1  = (const float*)d_in[14];
    const float* hW1 = (const float*)d_in[15];
    const float* hb1 = (const float*)d_in[16];
    const float* hg1 = (const float*)d_in[17];
    const float* hbb1= (const float*)d_in[18];
    const float* hm1 = (const float*)d_in[19];
    const float* hv1 = (const float*)d_in[20];
    const float* hW2 = (const float*)d_in[21];
    const float* hb2 = (const float*)d_in[22];
    const float* hg2 = (const float*)d_in[23];
    const float* hbb2= (const float*)d_in[24];
    const float* hm2 = (const float*)d_in[25];
    const float* hv2 = (const float*)d_in[26];
    const float* hW3 = (const float*)d_in[27];
    const float* hb3 = (const float*)d_in[28];
    const float* hW4 = (const float*)d_in[29];
    const float* hb4 = (const float*)d_in[30];
    float* out = (float*)d_out;

    const int* erow = ei;
    const int* ecol = ei + N_EDGES;

    float *p_xw = nullptr, *p_agg = nullptr;
    cudaGetSymbolAddress((void**)&p_xw, g_xw);
    cudaGetSymbolAddress((void**)&p_agg, g_agg);

    static cudaStream_t s_side = nullptr;
    static cudaEvent_t ev_fork = nullptr, ev_join = nullptr;
    if (s_side == nullptr) {
        cudaStreamCreateWithFlags(&s_side, cudaStreamNonBlocking);
        cudaEventCreateWithFlags(&ev_fork, cudaEventDisableTiming);
        cudaEventCreateWithFlags(&ev_join, cudaEventDisableTiming);
    }

    const int T = 256;
    int gN    = (N_NODES + T - 1) / T;
    int gE    = (N_EDGES + T - 1) / T;
    int gRows = (N_NODES + 63) / 64;
    int gAgg  = (int)(((long long)N_NODES * 32 + T - 1) / T);
    int gPool = (N_NODES + POOL_NODES - 1) / POOL_NODES;

    // ---- fork ----
    cudaEventRecord(ev_fork, 0);
    cudaStreamWaitEvent(s_side, ev_fork, 0);

    // side branch: CSR build (depends only on edge_index)
    k_init<<<gN, T, 0, s_side>>>();
    k_deg_count<<<gE, T, 0, s_side>>>(ecol);
    k_scan_partial<<<SBLOCKS, 256, 0, s_side>>>();
    k_scan_chunk<<<SBLOCKS, 256, 0, s_side>>>();
    k_place<<<gE, T, 0, s_side>>>(erow, ecol);
    cudaEventRecord(ev_join, s_side);

    // main branch: gemm0 (raw A@W, no dinv dependency) runs CONCURRENTLY
    k_gemm64<<<gRows, T>>>(x, gcn_W0, p_xw, 0);

    // ---- join: agg0 needs both gemm0 (main) and CSR (side) ----
    cudaStreamWaitEvent(0, ev_join, 0);

    // GCN layer 0: per-edge dinv normalization
    k_agg<<<gAgg, T>>>(gcn_b0, bn_g0, bn_b0, bn_m0, bn_v0, 1);

    // GCN layer 1: dinv folded into gemm output
    k_gemm64<<<gRows, T>>>(p_agg, gcn_W1, p_xw, 1);
    k_agg<<<gAgg, T>>>(gcn_b1, bn_g1, bn_b1, bn_m1, bn_v1, 0);

    // pool
    k_pool<<<gPool, 64>>>(batch);

    // MLP head
    k_mlp<<<NUM_GRAPHS, 256>>>(hW1, hb1, hg1, hbb1, hm1, hv1,
                               hW2, hb2, hg2, hbb2, hm2, hv2,
                               hW3, hb3, hW4, hb4, out);
}

// round 9
// speedup vs baseline: 1.2709x; 1.2709x over previous
#include <cuda_runtime.h>
#include <cuda_bf16.h>

#define N_NODES 50000
#define N_EDGES 800000
#define NUM_GRAPHS 256
#define D 64
#define EPS 1e-5f

#define SCHUNK 196
#define SBLOCKS 256   // 256*196 = 50176 >= 50000

// ---------------- scratch (device globals; no allocation) ----------------
__device__ float g_xw[N_NODES * D];      // dinv[n] * (A @ W)[n]
__device__ float g_agg[N_NODES * D];     // layer-0 output
__device__ float g_deg[N_NODES];         // 1 + in-degree (float)
__device__ float g_dinv[N_NODES];
__device__ int   g_esrc[N_EDGES];        // source ids, grouped by target (CSR)
__device__ int   g_startv[N_NODES];      // CSR row start
__device__ int   g_pos[N_NODES];         // placement cursor -> row end
__device__ int   g_part[SBLOCKS];
__device__ float g_pooled[NUM_GRAPHS * D];
__device__ float g_cnt[NUM_GRAPHS];

// ---------------- init: deg=1 (self-loop), zero pool, graph node counts ----------------
__global__ void k_init(const int* __restrict__ batch) {
    int i = blockIdx.x * blockDim.x + threadIdx.x;
    if (i < N_NODES) {
        g_deg[i] = 1.0f;
        atomicAdd(&g_cnt[batch[i]], 1.0f);   // g_cnt zeroed below first? -> no: zero then add needs ordering
    }
    if (i < NUM_GRAPHS * D) g_pooled[i] = 0.0f;
}

// zero cnt must happen before k_init's atomicAdd; do it in a micro-kernel.
__global__ void k_zero_cnt() {
    int i = threadIdx.x;
    if (i < NUM_GRAPHS) g_cnt[i] = 0.0f;
}

__global__ void k_deg_count(const int* __restrict__ col) {
    int e = blockIdx.x * blockDim.x + threadIdx.x;
    if (e < N_EDGES) atomicAdd(&g_deg[col[e]], 1.0f);
}

// ---------------- scan phase 1: per-chunk totals (+ dinv fused) ----------------
__global__ void k_scan_partial() {
    __shared__ int sh[256];
    int b = blockIdx.x, t = threadIdx.x;
    int n = b * SCHUNK + t;
    int v = 0;
    if (t < SCHUNK && n < N_NODES) {
        float d = g_deg[n];
        g_dinv[n] = rsqrtf(d);
        v = (int)d - 1;
    }
    sh[t] = v;
    __syncthreads();
    for (int off = 128; off > 0; off >>= 1) {
        if (t < off) sh[t] += sh[t + off];
        __syncthreads();
    }
    if (t == 0) g_part[b] = sh[0];
}

// ---------------- scan phase 2: chunk scan with inline base reduction ----------------
__global__ void k_scan_chunk() {
    __shared__ int sh[256];
    __shared__ int bs[256];
    int b = blockIdx.x, t = threadIdx.x;
    bs[t] = (t < b) ? g_part[t] : 0;
    int n = b * SCHUNK + t;
    int v = 0;
    if (t < SCHUNK && n < N_NODES) v = (int)g_deg[n] - 1;
    sh[t] = v;
    __syncthreads();
    for (int off = 128; off > 0; off >>= 1) {
        if (t < off) bs[t] += bs[t + off];
        __syncthreads();
    }
    for (int off = 1; off < 256; off <<= 1) {
        int add = (t >= off) ? sh[t - off] : 0;
        __syncthreads();
        sh[t] += add;
        __syncthreads();
    }
    if (t < SCHUNK && n < N_NODES) {
        int start = bs[0] + sh[t] - v;
        g_startv[n] = start;
        g_pos[n] = start;
    }
}

__global__ void k_place(const int* __restrict__ row, const int* __restrict__ col) {
    int e = blockIdx.x * blockDim.x + threadIdx.x;
    if (e >= N_EDGES) return;
    int c = col[e];
    int slot = atomicAdd(&g_pos[c], 1);
    g_esrc[slot] = row[e];
}

// ---------------- GEMM: C[n,:] = dinv[n] * (A[n,:] @ W)  (4x4 register tile) ----------------
__global__ void k_gemm64(const float* __restrict__ A,
                         const float* __restrict__ W,
                         float* __restrict__ C) {
    __shared__ float  As[64][65];
    __shared__ float4 Ws4[64][16];
    int tid = threadIdx.x;
    int row0 = blockIdx.x * 64;

    #pragma unroll
    for (int i = tid; i < 1024; i += 256)
        Ws4[i >> 4][i & 15] = ((const float4*)W)[i];
    #pragma unroll
    for (int i = tid; i < 4096; i += 256) {
        int r = i >> 6, c = i & 63;
        As[r][c] = (row0 + r < N_NODES) ? A[(row0 + r) * D + c] : 0.0f;
    }
    __syncthreads();

    int tx = tid & 15;
    int ty = tid >> 4;

    float4 acc0 = {0,0,0,0}, acc1 = {0,0,0,0}, acc2 = {0,0,0,0}, acc3 = {0,0,0,0};

    #pragma unroll
    for (int k = 0; k < 64; k++) {
        float4 w = Ws4[k][tx];
        float a0 = As[ty * 4 + 0][k];
        float a1 = As[ty * 4 + 1][k];
        float a2 = As[ty * 4 + 2][k];
        float a3 = As[ty * 4 + 3][k];
        acc0.x = fmaf(a0, w.x, acc0.x); acc0.y = fmaf(a0, w.y, acc0.y);
        acc0.z = fmaf(a0, w.z, acc0.z); acc0.w = fmaf(a0, w.w, acc0.w);
        acc1.x = fmaf(a1, w.x, acc1.x); acc1.y = fmaf(a1, w.y, acc1.y);
        acc1.z = fmaf(a1, w.z, acc1.z); acc1.w = fmaf(a1, w.w, acc1.w);
        acc2.x = fmaf(a2, w.x, acc2.x); acc2.y = fmaf(a2, w.y, acc2.y);
        acc2.z = fmaf(a2, w.z, acc2.z); acc2.w = fmaf(a2, w.w, acc2.w);
        acc3.x = fmaf(a3, w.x, acc3.x); acc3.y = fmaf(a3, w.y, acc3.y);
        acc3.z = fmaf(a3, w.z, acc3.z); acc3.w = fmaf(a3, w.w, acc3.w);
    }

    #pragma unroll
    for (int i = 0; i < 4; i++) {
        int r = row0 + ty * 4 + i;
        if (r < N_NODES) {
            float d = g_dinv[r];
            float4 v = (i == 0) ? acc0 : (i == 1) ? acc1 : (i == 2) ? acc2 : acc3;
            v.x *= d; v.y *= d; v.z *= d; v.w *= d;
            *((float4*)(C + r * D) + tx) = v;
        }
    }
}

// ---------------- gather-aggregate + self-loop + bias + BN + ReLU ----------------
// do_pool=0: write node row to g_agg.  do_pool=1: atomically accumulate the row
// into g_pooled[batch[w]] instead (fused global mean pool numerator).
__global__ void k_agg(const float* __restrict__ b,
                      const float* __restrict__ bg,
                      const float* __restrict__ bb,
                      const float* __restrict__ bm,
                      const float* __restrict__ bv,
                      const int* __restrict__ batch,
                      int do_pool) {
    int w = (blockIdx.x * blockDim.x + threadIdx.x) >> 5;
    int lane = threadIdx.x & 31;
    if (w >= N_NODES) return;
    int s0 = g_startv[w];
    int s1 = g_pos[w];
    int cb = 2 * lane;

    float2 acc = *(const float2*)(g_xw + w * D + cb);  // self-loop (dinv folded)
    for (int j = s0; j < s1; j++) {
        int r = __ldg(&g_esrc[j]);
        float2 v = *(const float2*)(g_xw + r * D + cb);
        acc.x += v.x;
        acc.y += v.y;
    }
    float dc = g_dinv[w];
    float2 bj  = *(const float2*)(b  + cb);
    float2 mj  = *(const float2*)(bm + cb);
    float2 vj  = *(const float2*)(bv + cb);
    float2 gj  = *(const float2*)(bg + cb);
    float2 bbj = *(const float2*)(bb + cb);
    float2 o;
    o.x = fmaxf((dc * acc.x + bj.x - mj.x) * rsqrtf(vj.x + EPS) * gj.x + bbj.x, 0.f);
    o.y = fmaxf((dc * acc.y + bj.y - mj.y) * rsqrtf(vj.y + EPS) * gj.y + bbj.y, 0.f);
    if (do_pool) {
        int g = __ldg(&batch[w]);
        atomicAdd(&g_pooled[g * D + cb],     o.x);
        atomicAdd(&g_pooled[g * D + cb + 1], o.y);
    } else {
        *(float2*)(g_agg + w * D + cb) = o;
    }
}

// ---------------- MLP head ----------------
__global__ void k_mlp(const float* __restrict__ hW1, const float* __restrict__ hb1,
                      const float* __restrict__ hg1, const float* __restrict__ hbb1,
                      const float* __restrict__ hm1, const float* __restrict__ hv1,
                      const float* __restrict__ hW2, const float* __restrict__ hb2,
                      const float* __restrict__ hg2, const float* __restrict__ hbb2,
                      const float* __restrict__ hm2, const float* __restrict__ hv2,
                      const float* __restrict__ hW3, const float* __restrict__ hb3,
                      const float* __restrict__ hW4, const float* __restrict__ hb4,
                      float* __restrict__ out) {
    __shared__ float p[64];
    __shared__ float z1[256];
    __shared__ float z2[128];
    __shared__ float z3[64];
    int g = blockIdx.x;
    int tid = threadIdx.x;
    if (tid < 64) {
        float c = fmaxf(g_cnt[g], 1.0f);
        p[tid] = g_pooled[g * D + tid] / c;
    }
    __syncthreads();
    {
        float acc = hb1[tid];
        #pragma unroll
        for (int k = 0; k < 64; k++) acc = fmaf(p[k], hW1[k * 256 + tid], acc);
        acc = (acc - hm1[tid]) * rsqrtf(hv1[tid] + EPS) * hg1[tid] + hbb1[tid];
        z1[tid] = fmaxf(acc, 0.0f);
    }
    __syncthreads();
    if (tid < 128) {
        float acc = hb2[tid];
        #pragma unroll 8
        for (int k = 0; k < 256; k++) acc = fmaf(z1[k], hW2[k * 128 + tid], acc);
        acc = (acc - hm2[tid]) * rsqrtf(hv2[tid] + EPS) * hg2[tid] + hbb2[tid];
        z2[tid] = fmaxf(acc, 0.0f);
    }
    __syncthreads();
    if (tid < 64) {
        float acc = hb3[tid];
        #pragma unroll 8
        for (int k = 0; k < 128; k++) acc = fmaf(z2[k], hW3[k * 64 + tid], acc);
        z3[tid] = fmaxf(acc, 0.0f);
    }
    __syncthreads();
    if (tid == 0) {
        float acc = hb4[0];
        #pragma unroll
        for (int k = 0; k < 64; k++) acc = fmaf(z3[k], hW4[k], acc);
        out[g] = acc;
    }
}

// ---------------- launch ----------------
extern "C" void kernel_launch(void* const* d_in, const int* in_sizes, int n_in,
                              void* d_out, int out_size) {
    const float* x      = (const float*)d_in[0];
    const int*   ei     = (const int*)d_in[1];
    const int*   batch  = (const int*)d_in[2];
    const float* gcn_W0 = (const float*)d_in[3];
    const float* gcn_b0 = (const float*)d_in[4];
    const float* bn_g0  = (const float*)d_in[5];
    const float* bn_b0  = (const float*)d_in[6];
    const float* bn_m0  = (const float*)d_in[7];
    const float* bn_v0  = (const float*)d_in[8];
    const float* gcn_W1 = (const float*)d_in[9];
    const float* gcn_b1 = (const float*)d_in[10];
    const float* bn_g1  = (const float*)d_in[11];
    const float* bn_b1  = (const float*)d_in[12];
    const float* bn_m1  = (const float*)d_in[13];
    const float* bn_v1  = (const float*)d_in[14];
    const float* hW1 = (const float*)d_in[15];
    const float* hb1 = (const float*)d_in[16];
    const float* hg1 = (const float*)d_in[17];
    const float* hbb1= (const float*)d_in[18];
    const float* hm1 = (const float*)d_in[19];
    const float* hv1 = (const float*)d_in[20];
    const float* hW2 = (const float*)d_in[21];
    const float* hb2 = (const float*)d_in[22];
    const float* hg2 = (const float*)d_in[23];
    const float* hbb2= (const float*)d_in[24];
    const float* hm2 = (const float*)d_in[25];
    const float* hv2 = (const float*)d_in[26];
    const float* hW3 = (const float*)d_in[27];
    const float* hb3 = (const float*)d_in[28];
    const float* hW4 = (const float*)d_in[29];
    const float* hb4 = (const float*)d_in[30];
    float* out = (float*)d_out;

    const int* erow = ei;
    const int* ecol = ei + N_EDGES;

    float *p_xw = nullptr, *p_agg = nullptr;
    cudaGetSymbolAddress((void**)&p_xw, g_xw);
    cudaGetSymbolAddress((void**)&p_agg, g_agg);

    const int T = 256;
    int gN    = (N_NODES + T - 1) / T;
    int gE    = (N_EDGES + T - 1) / T;
    int gRows = (N_NODES + 63) / 64;
    int gAgg  = (int)(((long long)N_NODES * 32 + T - 1) / T);

    // CSR build (serial — overlap with gemm0 showed no gain; gemm0 saturates SMs)
    k_zero_cnt<<<1, 256>>>();
    k_init<<<gN, T>>>(batch);
    k_deg_count<<<gE, T>>>(ecol);
    k_scan_partial<<<SBLOCKS, 256>>>();
    k_scan_chunk<<<SBLOCKS, 256>>>();
    k_place<<<gE, T>>>(erow, ecol);

    // GCN layer 0
    k_gemm64<<<gRows, T>>>(x, gcn_W0, p_xw);
    k_agg<<<gAgg, T>>>(gcn_b0, bn_g0, bn_b0, bn_m0, bn_v0, batch, 0);

    // GCN layer 1 (+ fused mean-pool numerator)
    k_gemm64<<<gRows, T>>>(p_agg, gcn_W1, p_xw);
    k_agg<<<gAgg, T>>>(gcn_b1, bn_g1, bn_b1, bn_m1, bn_v1, batch, 1);

    // MLP head
    k_mlp<<<NUM_GRAPHS, 256>>>(hW1, hb1, hg1, hbb1, hm1, hv1,
                               hW2, hb2, hg2, hbb2, hm2, hv2,
                               hW3, hb3, hW4, hb4, out);
}